// round 1
// baseline (speedup 1.0000x reference)
#include <cuda_runtime.h>
#include <math.h>

// Problem dims (fixed by the dataset)
#define NB     8
#define B_SZ   4
#define S_SZ   4096
#define DIN    2048
#define DHID   2048
#define DH     1024
#define MROWS  (B_SZ * S_SZ)   // 16384

// GEMM tile config
#define BM 128
#define BN 128
#define BK 16

// ---------------------------------------------------------------------------
// Scratch (device globals -- no allocation allowed in kernel_launch)
// ---------------------------------------------------------------------------
__device__ float g_xh [(size_t)MROWS * DHID];  // x @ W_in + b_in
__device__ float g_gx [(size_t)MROWS * DH];    // pre-sigmoid gate_x
__device__ float g_ga [(size_t)MROWS * DH];    // pre-sigmoid gate_a
__device__ float g_are[(size_t)MROWS * DH];
__device__ float g_aim[(size_t)MROWS * DH];
__device__ float g_xr [(size_t)MROWS * DH];
__device__ float g_xi [(size_t)MROWS * DH];
__device__ float g_h  [(size_t)MROWS * DHID];  // scan output [hr | hi]

// ---------------------------------------------------------------------------
// Shared 128x128 fp32 GEMM tile (8x8 per-thread, 256 threads)
// A row-major [.. x K] (pre-offset to block row), B row-major [K x ..]
// (pre-offset to block col). C = A*B + bias(col).
// ---------------------------------------------------------------------------
__device__ __forceinline__ void sgemm_tile(
    const float* __restrict__ A, int lda,
    const float* __restrict__ Bm, int ldb,
    const float* __restrict__ bias,
    float* __restrict__ C, int ldc, int K)
{
    __shared__ float As[BK][BM];
    __shared__ float Bs[BK][BN];
    const int tid = threadIdx.x;
    const int tx = tid & 15;
    const int ty = tid >> 4;

    float acc[8][8];
#pragma unroll
    for (int m = 0; m < 8; m++)
#pragma unroll
        for (int n = 0; n < 8; n++) acc[m][n] = 0.f;

    for (int kt = 0; kt < K; kt += BK) {
        // Load A tile (128 rows x 16 cols), store transposed
#pragma unroll
        for (int i = 0; i < 2; i++) {
            int f = tid + i * 256;
            int r = f >> 2;
            int c = (f & 3) << 2;
            float4 v = *reinterpret_cast<const float4*>(A + (size_t)r * lda + kt + c);
            As[c + 0][r] = v.x;
            As[c + 1][r] = v.y;
            As[c + 2][r] = v.z;
            As[c + 3][r] = v.w;
        }
        // Load B tile (16 rows x 128 cols)
#pragma unroll
        for (int i = 0; i < 2; i++) {
            int f = tid + i * 256;
            int r = f >> 5;
            int c = (f & 31) << 2;
            *reinterpret_cast<float4*>(&Bs[r][c]) =
                *reinterpret_cast<const float4*>(Bm + (size_t)(kt + r) * ldb + c);
        }
        __syncthreads();
#pragma unroll
        for (int k = 0; k < BK; k++) {
            float4 a0 = *reinterpret_cast<const float4*>(&As[k][ty * 8]);
            float4 a1 = *reinterpret_cast<const float4*>(&As[k][ty * 8 + 4]);
            float4 b0 = *reinterpret_cast<const float4*>(&Bs[k][tx * 8]);
            float4 b1 = *reinterpret_cast<const float4*>(&Bs[k][tx * 8 + 4]);
            float ra[8] = {a0.x, a0.y, a0.z, a0.w, a1.x, a1.y, a1.z, a1.w};
            float rb[8] = {b0.x, b0.y, b0.z, b0.w, b1.x, b1.y, b1.z, b1.w};
#pragma unroll
            for (int m = 0; m < 8; m++)
#pragma unroll
                for (int n = 0; n < 8; n++)
                    acc[m][n] = fmaf(ra[m], rb[n], acc[m][n]);
        }
        __syncthreads();
    }

#pragma unroll
    for (int m = 0; m < 8; m++) {
        int r = ty * 8 + m;
#pragma unroll
        for (int n = 0; n < 8; n += 4) {
            int c = tx * 8 + n;
            float4 o;
            o.x = acc[m][n + 0] + bias[c + 0];
            o.y = acc[m][n + 1] + bias[c + 1];
            o.z = acc[m][n + 2] + bias[c + 2];
            o.w = acc[m][n + 3] + bias[c + 3];
            *reinterpret_cast<float4*>(C + (size_t)r * ldc + c) = o;
        }
    }
}

// Dense GEMM: C[M x N] = A[M x K] @ B[K x N] + bias
__global__ __launch_bounds__(256) void sgemm_kernel(
    const float* __restrict__ A, const float* __restrict__ Bm,
    const float* __restrict__ bias, float* __restrict__ C, int K, int N)
{
    const float* Ab = A + (size_t)blockIdx.y * BM * K;
    const float* Bb = Bm + (size_t)blockIdx.x * BN;
    float* Cb = C + (size_t)blockIdx.y * BM * N + (size_t)blockIdx.x * BN;
    sgemm_tile(Ab, K, Bb, N, bias + blockIdx.x * BN, Cb, N, K);
}

// Block-diagonal gate GEMMs: for each of 8 blocks, [16384 x 256] @ [256 x 128]
// grid = (MROWS/BM, NB, 2); z selects gate_x vs gate_a weights.
__global__ __launch_bounds__(256) void blockdiag_kernel(
    const float* __restrict__ xh,
    const float* __restrict__ Wgx, const float* __restrict__ bgx,
    const float* __restrict__ Wga, const float* __restrict__ bga,
    float* __restrict__ gx, float* __restrict__ ga)
{
    const int nb = blockIdx.y;
    const int which = blockIdx.z;
    const float* W    = which ? Wga : Wgx;
    const float* bias = which ? bga : bgx;
    float*       out  = which ? ga  : gx;
    const float* Ab = xh + (size_t)blockIdx.x * BM * DHID + nb * 256;
    const float* Bb = W + (size_t)nb * 256 * 128;
    float* Cb = out + (size_t)blockIdx.x * BM * DH + nb * 128;
    sgemm_tile(Ab, DHID, Bb, 128, bias + nb * 128, Cb, DH, 256);
}

// ---------------------------------------------------------------------------
// Pointwise: gates -> a_re, a_im, gated/normalized xr, xi
// ---------------------------------------------------------------------------
__global__ __launch_bounds__(256) void pointwise_kernel(
    const float* __restrict__ xh,
    const float* __restrict__ gxl, const float* __restrict__ gal,
    const float* __restrict__ arp, const float* __restrict__ aip,
    float* __restrict__ are, float* __restrict__ aim,
    float* __restrict__ xr, float* __restrict__ xi)
{
    size_t e = (size_t)blockIdx.x * blockDim.x + threadIdx.x;
    int d = (int)(e & (DH - 1));
    size_t row = e >> 10;

    float gxv = 1.f / (1.f + expf(-gxl[e]));
    float gav = 1.f / (1.f + expf(-gal[e]));
    float v = arp[d];
    float sp = fmaxf(v, 0.f) + log1pf(expf(-fabsf(v)));  // softplus
    float log_a = -8.f * gav * sp;
    float mag = expf(log_a);
    float th = aip[d] * gav;
    float sn, cs;
    sincosf(th, &sn, &cs);
    float asq = mag * mag;                 // exp(2*log_a)
    float nrm = sqrtf(fmaxf(1.f - asq, 0.f));
    float scale = gxv * nrm;

    size_t xrow = row * DHID + d;
    are[e] = mag * cs;
    aim[e] = mag * sn;
    xr[e] = scale * xh[xrow];
    xi[e] = scale * xh[xrow + DH];
}

// ---------------------------------------------------------------------------
// Sequential complex scan along S, one thread per (b, d) chain.
// Coalesced: at step s, adjacent threads (adjacent d) touch adjacent floats.
// Writes h = [hr | hi] rows and h_last at s = S-1.
// ---------------------------------------------------------------------------
__global__ __launch_bounds__(128) void scan_kernel(
    const float* __restrict__ are, const float* __restrict__ aim,
    const float* __restrict__ xr, const float* __restrict__ xi,
    float* __restrict__ h, float* __restrict__ h_last)
{
    int chain = blockIdx.x * blockDim.x + threadIdx.x;  // 0..4095
    int b = chain >> 10;
    int d = chain & (DH - 1);
    float hr = 0.f, hi = 0.f;
    size_t base  = (size_t)b * S_SZ * DH + d;
    size_t hbase = (size_t)b * S_SZ * DHID + d;

#pragma unroll 4
    for (int s = 0; s < S_SZ; s++) {
        size_t idx = base + (size_t)s * DH;
        float ar = are[idx];
        float ai = aim[idx];
        float vr = xr[idx];
        float vi = xi[idx];
        float nhr = fmaf(ar, hr, fmaf(-ai, hi, vr));
        float nhi = fmaf(ar, hi, fmaf(ai, hr, vi));
        hr = nhr;
        hi = nhi;
        size_t hrow = hbase + (size_t)s * DHID;
        h[hrow]      = hr;
        h[hrow + DH] = hi;
    }
    h_last[(size_t)b * DHID + d]      = hr;
    h_last[(size_t)b * DHID + d + DH] = hi;
}

// ---------------------------------------------------------------------------
// Launch
// ---------------------------------------------------------------------------
extern "C" void kernel_launch(void* const* d_in, const int* in_sizes, int n_in,
                              void* d_out, int out_size)
{
    const float* x     = (const float*)d_in[0];
    const float* arp   = (const float*)d_in[1];
    const float* aip   = (const float*)d_in[2];
    const float* W_in  = (const float*)d_in[3];
    const float* b_in  = (const float*)d_in[4];
    const float* Wgx   = (const float*)d_in[5];
    const float* bgx   = (const float*)d_in[6];
    const float* Wga   = (const float*)d_in[7];
    const float* bga   = (const float*)d_in[8];
    const float* W_out = (const float*)d_in[9];
    const float* b_out = (const float*)d_in[10];

    float* y = (float*)d_out;
    float* h_last = (float*)d_out + ((size_t)out_size - (size_t)B_SZ * DHID);

    float *xh, *gx, *ga, *are, *aim, *xr, *xi, *h;
    cudaGetSymbolAddress((void**)&xh,  g_xh);
    cudaGetSymbolAddress((void**)&gx,  g_gx);
    cudaGetSymbolAddress((void**)&ga,  g_ga);
    cudaGetSymbolAddress((void**)&are, g_are);
    cudaGetSymbolAddress((void**)&aim, g_aim);
    cudaGetSymbolAddress((void**)&xr,  g_xr);
    cudaGetSymbolAddress((void**)&xi,  g_xi);
    cudaGetSymbolAddress((void**)&h,   g_h);

    dim3 blk(256);

    // 1) x_h = x @ W_in + b_in   [16384 x 2048]
    sgemm_kernel<<<dim3(DHID / BN, MROWS / BM), blk>>>(x, W_in, b_in, xh, DIN, DHID);

    // 2) gate linears (block-diagonal), bias added in epilogue
    blockdiag_kernel<<<dim3(MROWS / BM, NB, 2), blk>>>(xh, Wgx, bgx, Wga, bga, gx, ga);

    // 3) pointwise: produce a_re, a_im, xr, xi
    pointwise_kernel<<<(MROWS * (size_t)DH) / 256, 256>>>(xh, gx, ga, arp, aip,
                                                          are, aim, xr, xi);

    // 4) complex linear scan along S
    scan_kernel<<<(B_SZ * DH) / 128, 128>>>(are, aim, xr, xi, h, h_last);

    // 5) y = h @ W_out + b_out   [16384 x 2048]
    sgemm_kernel<<<dim3(DIN / BN, MROWS / BM), blk>>>(h, W_out, b_out, y, DHID, DIN);
}